// round 8
// baseline (speedup 1.0000x reference)
#include <cuda_runtime.h>
#include <cuda_bf16.h>

// Problem constants (fixed by the reference)
#define HS_N    4096
#define HS_P    10
#define HS_D    17
#define HS_PD   (HS_P * HS_D)   // 170 dot products per sample
#define HS_DIM  300             // embedding dim (75 float4)
#define HS_VEC4 (HS_DIM / 4)    // 75
#define PSTRIDE 33              // padded partials stride (conflict-free)

__device__ __forceinline__ float dot4(float4 a, float4 b) {
    return a.x * b.x + a.y * b.y + a.z * b.z + a.w * b.w;
}

__device__ __forceinline__ void emit(float s, int pos,
                                     const int* __restrict__ labels,
                                     float* __restrict__ out,
                                     float* __restrict__ target) {
    const float o = 1.0f / (1.0f + expf(-s));
    // Threshold the f32 sigmoid VALUE (matches reference rounding at 0.5).
    const int m = (o >= 0.5f) ? 1 : 0;
    const int l = labels[pos];
    out[pos]    = o;
    target[pos] = (m == l) ? 1.0f : 0.0f;
}

__global__ __launch_bounds__(256)
void skip_gram_hs_kernel(const int*   __restrict__ word_idx,   // [N]
                         const int*   __restrict__ paths,      // [N, P, D]
                         const int*   __restrict__ labels,     // [N, P, D]
                         const float* __restrict__ emb1,       // [VOCAB, DIM]
                         const float* __restrict__ emb2,       // [VOCAB-1, DIM]
                         float*       __restrict__ out,        // [N, P, D] sigmoid
                         float*       __restrict__ target)     // [N, P, D]
{
    __shared__ float s_part[HS_PD * PSTRIDE];   // 170*33*4 = 22440 B

    const int n    = blockIdx.x;
    const int tid  = threadIdx.x;
    const int warp = tid >> 5;
    const int lane = tid & 31;
    const bool tail = (lane < HS_VEC4 - 64);    // lanes 0..10 own float4 #64..74

    // proj = emb1[word_idx[n]] in registers per lane.
    const int w = __ldg(word_idx + n);
    const float4* __restrict__ prow =
        reinterpret_cast<const float4*>(emb1 + (size_t)w * HS_DIM);
    const float4 p0 = __ldg(prow + lane);
    const float4 p1 = __ldg(prow + lane + 32);
    const float4 p2 = tail ? __ldg(prow + lane + 64) : make_float4(0.f, 0.f, 0.f, 0.f);

    const int base = n * HS_PD;
    const float4 z = make_float4(0.f, 0.f, 0.f, 0.f);

    // ── Phase 1: stream loads, write per-lane partials to shared.
    // No shuffle chain in this loop -> iterations are load-independent.
    {
        int k = warp;
        for (; k + 8 < HS_PD; k += 16) {
            const int i0 = __ldg(paths + base + k);
            const int i1 = __ldg(paths + base + k + 8);
            const float4* __restrict__ r0 =
                reinterpret_cast<const float4*>(emb2 + (size_t)i0 * HS_DIM);
            const float4* __restrict__ r1 =
                reinterpret_cast<const float4*>(emb2 + (size_t)i1 * HS_DIM);

            float4 a0 = __ldg(r0 + lane), a1 = __ldg(r0 + lane + 32);
            float4 b0 = __ldg(r1 + lane), b1 = __ldg(r1 + lane + 32);
            float4 a2 = z, b2 = z;
            if (tail) { a2 = __ldg(r0 + lane + 64); b2 = __ldg(r1 + lane + 64); }

            const float s0 = dot4(a0, p0) + dot4(a1, p1) + dot4(a2, p2);
            const float s1 = dot4(b0, p0) + dot4(b1, p1) + dot4(b2, p2);

            s_part[k * PSTRIDE + lane]       = s0;   // bank (k+lane)%32: conflict-free
            s_part[(k + 8) * PSTRIDE + lane] = s1;
        }
        if (k < HS_PD) {
            const int idx = __ldg(paths + base + k);
            const float4* __restrict__ row =
                reinterpret_cast<const float4*>(emb2 + (size_t)idx * HS_DIM);
            float4 a0 = __ldg(row + lane), a1 = __ldg(row + lane + 32);
            float4 a2 = z;
            if (tail) a2 = __ldg(row + lane + 64);
            s_part[k * PSTRIDE + lane] =
                dot4(a0, p0) + dot4(a1, p1) + dot4(a2, p2);
        }
    }

    __syncthreads();

    // ── Phase 2: butterfly-reduce partials (identical tree to the passing
    // R5 kernel -> bit-identical results). 4-way interleaved chains; no
    // global loads compete here.
    {
        int k = warp;
        for (; k + 24 < HS_PD; k += 32) {
            float s0 = s_part[k * PSTRIDE + lane];
            float s1 = s_part[(k + 8)  * PSTRIDE + lane];
            float s2 = s_part[(k + 16) * PSTRIDE + lane];
            float s3 = s_part[(k + 24) * PSTRIDE + lane];

            #pragma unroll
            for (int off = 16; off > 0; off >>= 1) {
                s0 += __shfl_xor_sync(0xffffffffu, s0, off);
                s1 += __shfl_xor_sync(0xffffffffu, s1, off);
                s2 += __shfl_xor_sync(0xffffffffu, s2, off);
                s3 += __shfl_xor_sync(0xffffffffu, s3, off);
            }
            if (lane == 0) {
                emit(s0, base + k,      labels, out, target);
                emit(s1, base + k + 8,  labels, out, target);
                emit(s2, base + k + 16, labels, out, target);
                emit(s3, base + k + 24, labels, out, target);
            }
        }
        for (; k + 8 < HS_PD; k += 16) {
            float s0 = s_part[k * PSTRIDE + lane];
            float s1 = s_part[(k + 8) * PSTRIDE + lane];
            #pragma unroll
            for (int off = 16; off > 0; off >>= 1) {
                s0 += __shfl_xor_sync(0xffffffffu, s0, off);
                s1 += __shfl_xor_sync(0xffffffffu, s1, off);
            }
            if (lane == 0) {
                emit(s0, base + k,     labels, out, target);
                emit(s1, base + k + 8, labels, out, target);
            }
        }
        if (k < HS_PD) {
            float s = s_part[k * PSTRIDE + lane];
            #pragma unroll
            for (int off = 16; off > 0; off >>= 1)
                s += __shfl_xor_sync(0xffffffffu, s, off);
            if (lane == 0) emit(s, base + k, labels, out, target);
        }
    }
}

extern "C" void kernel_launch(void* const* d_in, const int* in_sizes, int n_in,
                              void* d_out, int out_size)
{
    // metadata order: word_idx, paths, labels, emb1, emb2
    const int*   word_idx = (const int*)  d_in[0];
    const int*   paths    = (const int*)  d_in[1];
    const int*   labels   = (const int*)  d_in[2];
    const float* emb1     = (const float*)d_in[3];
    const float* emb2     = (const float*)d_in[4];

    float* out    = (float*)d_out;                        // first N*P*D: sigmoid
    float* target = (float*)d_out + (size_t)HS_N * HS_PD; // second N*P*D: target

    skip_gram_hs_kernel<<<HS_N, 256>>>(word_idx, paths, labels, emb1, emb2,
                                       out, target);
}

// round 10
// speedup vs baseline: 1.0420x; 1.0420x over previous
#include <cuda_runtime.h>
#include <cuda_bf16.h>
#include <cstdint>

// Problem constants (fixed by the reference)
#define HS_N    4096
#define HS_P    10
#define HS_D    17
#define HS_PD   (HS_P * HS_D)   // 170 dot products per sample
#define HS_DIM  300             // embedding dim (75 float4)
#define HS_VEC4 (HS_DIM / 4)    // 75

__device__ __forceinline__ float dot4(float4 a, float4 b) {
    return a.x * b.x + a.y * b.y + a.z * b.z + a.w * b.w;
}

// emb2 row load with L2 evict_last policy: keeps the 120MB table resident in
// the 126MB L2 against streaming traffic.
__device__ __forceinline__ float4 ldg_pol(const float4* p, unsigned long long pol) {
    float4 v;
    asm("ld.global.nc.L2::cache_hint.v4.f32 {%0,%1,%2,%3}, [%4], %5;"
        : "=f"(v.x), "=f"(v.y), "=f"(v.z), "=f"(v.w)
        : "l"(p), "l"(pol));
    return v;
}

__device__ __forceinline__ void emit(float s, int pos,
                                     const int* __restrict__ labels,
                                     float* __restrict__ out,
                                     float* __restrict__ target) {
    const float o = 1.0f / (1.0f + expf(-s));
    // Threshold the f32 sigmoid VALUE (matches reference rounding at 0.5).
    const int m = (o >= 0.5f) ? 1 : 0;
    const int l = labels[pos];
    __stcs(out + pos, o);                          // streaming store: don't pollute L2
    __stcs(target + pos, (m == l) ? 1.0f : 0.0f);
}

struct Pair {
    float4 a0, a1, a2;   // row for k
    float4 b0, b1, b2;   // row for k+8 (duplicated row if k+8 invalid)
};

__global__ __launch_bounds__(256)
void skip_gram_hs_kernel(const int*   __restrict__ word_idx,   // [N]
                         const int*   __restrict__ paths,      // [N, P, D]
                         const int*   __restrict__ labels,     // [N, P, D]
                         const float* __restrict__ emb1,       // [VOCAB, DIM]
                         const float* __restrict__ emb2,       // [VOCAB-1, DIM]
                         float*       __restrict__ out,        // [N, P, D]
                         float*       __restrict__ target)     // [N, P, D]
{
    const int n    = blockIdx.x;
    const int tid  = threadIdx.x;
    const int warp = tid >> 5;
    const int lane = tid & 31;
    const bool tail = (lane < HS_VEC4 - 64);    // lanes 0..10 own float4 #64..74

    unsigned long long pol;
    asm("createpolicy.fractional.L2::evict_last.b64 %0, 1.0;" : "=l"(pol));

    // proj = emb1[word_idx[n]] in registers per lane.
    const int w = __ldg(word_idx + n);
    const float4* __restrict__ prow =
        reinterpret_cast<const float4*>(emb1 + (size_t)w * HS_DIM);
    const float4 p0 = __ldg(prow + lane);
    const float4 p1 = __ldg(prow + lane + 32);
    const float4 p2 = tail ? __ldg(prow + lane + 64) : make_float4(0.f, 0.f, 0.f, 0.f);

    const int base = n * HS_PD;
    const float4 z = make_float4(0.f, 0.f, 0.f, 0.f);

    // Stage s covers k = warp + 16*s and k+8. All warps have exactly 11 stages
    // (ceil((170 - warp)/16) == 11 for warp in 0..7).
    auto load_pair = [&](Pair& P, int k) {
        const int i0 = __ldg(paths + base + k);
        const int i1 = (k + 8 < HS_PD) ? __ldg(paths + base + k + 8) : i0;
        const float4* __restrict__ r0 =
            reinterpret_cast<const float4*>(emb2 + (size_t)i0 * HS_DIM);
        const float4* __restrict__ r1 =
            reinterpret_cast<const float4*>(emb2 + (size_t)i1 * HS_DIM);
        P.a0 = ldg_pol(r0 + lane, pol);
        P.a1 = ldg_pol(r0 + lane + 32, pol);
        P.b0 = ldg_pol(r1 + lane, pol);
        P.b1 = ldg_pol(r1 + lane + 32, pol);
        P.a2 = z; P.b2 = z;
        if (tail) {
            P.a2 = ldg_pol(r0 + lane + 64, pol);
            P.b2 = ldg_pol(r1 + lane + 64, pol);
        }
    };

    auto consume_pair = [&](const Pair& P, int k) {
        float s0 = dot4(P.a0, p0) + dot4(P.a1, p1) + dot4(P.a2, p2);
        float s1 = dot4(P.b0, p0) + dot4(P.b1, p1) + dot4(P.b2, p2);
        #pragma unroll
        for (int off = 16; off > 0; off >>= 1) {
            s0 += __shfl_xor_sync(0xffffffffu, s0, off);
            s1 += __shfl_xor_sync(0xffffffffu, s1, off);
        }
        if (lane == 0) {
            emit(s0, base + k, labels, out, target);
            if (k + 8 < HS_PD)
                emit(s1, base + k + 8, labels, out, target);
        }
    };

    // Ping-pong software pipeline: loads for stage s+1 are in flight while
    // stage s's shuffle chain drains. 11 stages = prologue + 5x2 + epilogue.
    Pair A, B;
    load_pair(A, warp);                         // stage 0
    #pragma unroll
    for (int s = 0; s < 10; s += 2) {
        load_pair(B, warp + 16 * (s + 1));      // stage s+1 in flight
        consume_pair(A, warp + 16 * s);         // drain stage s
        load_pair(A, warp + 16 * (s + 2));      // stage s+2 in flight
        consume_pair(B, warp + 16 * (s + 1));   // drain stage s+1
    }
    consume_pair(A, warp + 160);                // stage 10
}

extern "C" void kernel_launch(void* const* d_in, const int* in_sizes, int n_in,
                              void* d_out, int out_size)
{
    // metadata order: word_idx, paths, labels, emb1, emb2
    const int*   word_idx = (const int*)  d_in[0];
    const int*   paths    = (const int*)  d_in[1];
    const int*   labels   = (const int*)  d_in[2];
    const float* emb1     = (const float*)d_in[3];
    const float* emb2     = (const float*)d_in[4];

    float* out    = (float*)d_out;                        // first N*P*D: sigmoid
    float* target = (float*)d_out + (size_t)HS_N * HS_PD; // second N*P*D: target

    skip_gram_hs_kernel<<<HS_N, 256>>>(word_idx, paths, labels, emb1, emb2,
                                       out, target);
}

// round 11
// speedup vs baseline: 1.1047x; 1.0601x over previous
#include <cuda_runtime.h>
#include <cuda_bf16.h>

// Problem constants (fixed by the reference)
#define HS_N    4096
#define HS_P    10
#define HS_D    17
#define HS_PD   (HS_P * HS_D)   // 170 dot products per sample
#define HS_DIM  300             // embedding dim (75 float4)
#define HS_VEC4 (HS_DIM / 4)    // 75
#define PSTRIDE 32              // bank = lane -> conflict-free

__device__ __forceinline__ float dot4(float4 a, float4 b) {
    return a.x * b.x + a.y * b.y + a.z * b.z + a.w * b.w;
}

__device__ __forceinline__ void emit(float s, int pos,
                                     const int* __restrict__ labels,
                                     float* __restrict__ out,
                                     float* __restrict__ target) {
    const float o = 1.0f / (1.0f + expf(-s));
    // Threshold the f32 sigmoid VALUE (matches reference rounding at 0.5).
    const int m = (o >= 0.5f) ? 1 : 0;
    const int l = labels[pos];
    out[pos]    = o;
    target[pos] = (m == l) ? 1.0f : 0.0f;
}

__global__ __launch_bounds__(256)
void skip_gram_hs_kernel(const int*   __restrict__ word_idx,   // [N]
                         const int*   __restrict__ paths,      // [N, P, D]
                         const int*   __restrict__ labels,     // [N, P, D]
                         const float* __restrict__ emb1,       // [VOCAB, DIM]
                         const float* __restrict__ emb2,       // [VOCAB-1, DIM]
                         float*       __restrict__ out,        // [N, P, D]
                         float*       __restrict__ target)     // [N, P, D]
{
    // Per-thread accumulator spill space. Warp w touches only k in
    // {w, w+8, ...}; each THREAD reads back exactly the slot it wrote,
    // so NO barrier is needed between the phases (R7's __syncthreads was
    // the regression: block-wide wait on the slowest warp's DRAM misses).
    __shared__ float s_part[HS_PD * PSTRIDE];   // 21760 B

    const int n    = blockIdx.x;
    const int tid  = threadIdx.x;
    const int warp = tid >> 5;
    const int lane = tid & 31;
    const bool tail = (lane < HS_VEC4 - 64);    // lanes 0..10 own float4 #64..74

    // proj = emb1[word_idx[n]] in registers per lane.
    const int w = __ldg(word_idx + n);
    const float4* __restrict__ prow =
        reinterpret_cast<const float4*>(emb1 + (size_t)w * HS_DIM);
    const float4 p0 = __ldg(prow + lane);
    const float4 p1 = __ldg(prow + lane + 32);
    const float4 p2 = tail ? __ldg(prow + lane + 64) : make_float4(0.f, 0.f, 0.f, 0.f);

    const int base = n * HS_PD;
    const float4 z = make_float4(0.f, 0.f, 0.f, 0.f);

    // ── Phase 1: stream loads, write per-lane partials to shared.
    // Loop body has no shuffle chain -- only short FMA+STS consumers, so
    // exposed latency per iteration is just the load scoreboard wait.
    {
        int k = warp;
        for (; k + 8 < HS_PD; k += 16) {
            const int i0 = __ldg(paths + base + k);
            const int i1 = __ldg(paths + base + k + 8);
            const float4* __restrict__ r0 =
                reinterpret_cast<const float4*>(emb2 + (size_t)i0 * HS_DIM);
            const float4* __restrict__ r1 =
                reinterpret_cast<const float4*>(emb2 + (size_t)i1 * HS_DIM);

            float4 a0 = __ldg(r0 + lane), a1 = __ldg(r0 + lane + 32);
            float4 b0 = __ldg(r1 + lane), b1 = __ldg(r1 + lane + 32);
            float4 a2 = z, b2 = z;
            if (tail) { a2 = __ldg(r0 + lane + 64); b2 = __ldg(r1 + lane + 64); }

            s_part[k * PSTRIDE + lane] =
                dot4(a0, p0) + dot4(a1, p1) + dot4(a2, p2);
            s_part[(k + 8) * PSTRIDE + lane] =
                dot4(b0, p0) + dot4(b1, p1) + dot4(b2, p2);
        }
        if (k < HS_PD) {   // warps 0,1: k = 168,169
            const int idx = __ldg(paths + base + k);
            const float4* __restrict__ row =
                reinterpret_cast<const float4*>(emb2 + (size_t)idx * HS_DIM);
            float4 a0 = __ldg(row + lane), a1 = __ldg(row + lane + 32);
            float4 a2 = z;
            if (tail) a2 = __ldg(row + lane + 64);
            s_part[k * PSTRIDE + lane] =
                dot4(a0, p0) + dot4(a1, p1) + dot4(a2, p2);
        }
    }

    // ── Phase 2 (no barrier): butterfly-reduce this warp's own partials.
    // Identical reduction tree to R5 -> bit-identical outputs.
    {
        int k = warp;
        for (; k + 24 < HS_PD; k += 32) {
            float s0 = s_part[k * PSTRIDE + lane];
            float s1 = s_part[(k + 8)  * PSTRIDE + lane];
            float s2 = s_part[(k + 16) * PSTRIDE + lane];
            float s3 = s_part[(k + 24) * PSTRIDE + lane];

            #pragma unroll
            for (int off = 16; off > 0; off >>= 1) {
                s0 += __shfl_xor_sync(0xffffffffu, s0, off);
                s1 += __shfl_xor_sync(0xffffffffu, s1, off);
                s2 += __shfl_xor_sync(0xffffffffu, s2, off);
                s3 += __shfl_xor_sync(0xffffffffu, s3, off);
            }
            if (lane == 0) {
                emit(s0, base + k,      labels, out, target);
                emit(s1, base + k + 8,  labels, out, target);
                emit(s2, base + k + 16, labels, out, target);
                emit(s3, base + k + 24, labels, out, target);
            }
        }
        for (; k + 8 < HS_PD; k += 16) {
            float s0 = s_part[k * PSTRIDE + lane];
            float s1 = s_part[(k + 8) * PSTRIDE + lane];
            #pragma unroll
            for (int off = 16; off > 0; off >>= 1) {
                s0 += __shfl_xor_sync(0xffffffffu, s0, off);
                s1 += __shfl_xor_sync(0xffffffffu, s1, off);
            }
            if (lane == 0) {
                emit(s0, base + k,     labels, out, target);
                emit(s1, base + k + 8, labels, out, target);
            }
        }
        if (k < HS_PD) {
            float s = s_part[k * PSTRIDE + lane];
            #pragma unroll
            for (int off = 16; off > 0; off >>= 1)
                s += __shfl_xor_sync(0xffffffffu, s, off);
            if (lane == 0) emit(s, base + k, labels, out, target);
        }
    }
}

extern "C" void kernel_launch(void* const* d_in, const int* in_sizes, int n_in,
                              void* d_out, int out_size)
{
    // metadata order: word_idx, paths, labels, emb1, emb2
    const int*   word_idx = (const int*)  d_in[0];
    const int*   paths    = (const int*)  d_in[1];
    const int*   labels   = (const int*)  d_in[2];
    const float* emb1     = (const float*)d_in[3];
    const float* emb2     = (const float*)d_in[4];

    float* out    = (float*)d_out;                        // first N*P*D: sigmoid
    float* target = (float*)d_out + (size_t)HS_N * HS_PD; // second N*P*D: target

    skip_gram_hs_kernel<<<HS_N, 256>>>(word_idx, paths, labels, emb1, emb2,
                                       out, target);
}

// round 13
// speedup vs baseline: 1.1429x; 1.0346x over previous
#include <cuda_runtime.h>

// Problem constants (fixed by the reference)
#define HS_N    4096
#define HS_P    10
#define HS_D    17
#define HS_PD   (HS_P * HS_D)   // 170 dot products per sample
#define HS_DIM  300             // embedding dim (75 float4)
#define HS_VEC4 (HS_DIM / 4)    // 75

__device__ __forceinline__ float dot4(float4 a, float4 b) {
    return a.x * b.x + a.y * b.y + a.z * b.z + a.w * b.w;
}

// Emit with the label ALREADY loaded (prefetched at iteration top, so the
// L2 hop for the label overlaps the row loads + shuffle chain instead of
// sitting on the store's critical path).
__device__ __forceinline__ void emit_pl(float s, int pos, int l,
                                        float* __restrict__ out,
                                        float* __restrict__ target) {
    const float o = 1.0f / (1.0f + expf(-s));
    // Threshold the f32 sigmoid VALUE (matches reference rounding at 0.5).
    const int m = (o >= 0.5f) ? 1 : 0;
    __stcs(out + pos, o);                           // streaming: write-once data
    __stcs(target + pos, (m == l) ? 1.0f : 0.0f);
}

__global__ __launch_bounds__(256)
void skip_gram_hs_kernel(const int*   __restrict__ word_idx,   // [N]
                         const int*   __restrict__ paths,      // [N, P, D]
                         const int*   __restrict__ labels,     // [N, P, D]
                         const float* __restrict__ emb1,       // [VOCAB, DIM]
                         const float* __restrict__ emb2,       // [VOCAB-1, DIM]
                         float*       __restrict__ out,        // [N, P, D]
                         float*       __restrict__ target)     // [N, P, D]
{
    const int n    = blockIdx.x;
    const int tid  = threadIdx.x;
    const int warp = tid >> 5;
    const int lane = tid & 31;
    const bool tail = (lane < HS_VEC4 - 64);   // lanes 0..10 own float4 #64..74

    // proj = emb1[word_idx[n]] in registers per lane.
    const int w = __ldg(word_idx + n);
    const float4* __restrict__ prow =
        reinterpret_cast<const float4*>(emb1 + (size_t)w * HS_DIM);
    const float4 p0 = __ldg(prow + lane);
    const float4 p1 = __ldg(prow + lane + 32);
    const float4 p2 = tail ? __ldg(prow + lane + 64) : make_float4(0.f, 0.f, 0.f, 0.f);

    const int base = n * HS_PD;
    const float4 z = make_float4(0.f, 0.f, 0.f, 0.f);

    // 8 warps; each processes k = warp, warp+8, ... (~21 dot products),
    // two at a time for load MLP.
    int k = warp;
    for (; k + 8 < HS_PD; k += 16) {
        // Prefetch indices AND labels first: their latency hides under the
        // row loads + shuffle chain.
        const int idx0 = __ldg(paths + base + k);
        const int idx1 = __ldg(paths + base + k + 8);
        const int l0   = __ldg(labels + base + k);
        const int l1   = __ldg(labels + base + k + 8);

        const float4* __restrict__ r0 =
            reinterpret_cast<const float4*>(emb2 + (size_t)idx0 * HS_DIM);
        const float4* __restrict__ r1 =
            reinterpret_cast<const float4*>(emb2 + (size_t)idx1 * HS_DIM);

        // Issue all 6 wide loads before consuming.
        float4 a0 = __ldg(r0 + lane);
        float4 a1 = __ldg(r0 + lane + 32);
        float4 b0 = __ldg(r1 + lane);
        float4 b1 = __ldg(r1 + lane + 32);
        float4 a2 = z, b2 = z;
        if (tail) { a2 = __ldg(r0 + lane + 64); b2 = __ldg(r1 + lane + 64); }

        float s0 = dot4(a0, p0) + dot4(a1, p1) + dot4(a2, p2);
        float s1 = dot4(b0, p0) + dot4(b1, p1) + dot4(b2, p2);

        // Two independent butterfly chains, interleaved (identical tree to
        // the passing R5 kernel -> bit-identical results; sum lands in ALL
        // lanes).
        #pragma unroll
        for (int off = 16; off > 0; off >>= 1) {
            s0 += __shfl_xor_sync(0xffffffffu, s0, off);
            s1 += __shfl_xor_sync(0xffffffffu, s1, off);
        }

        // Emit split: lane 0 handles s0 while lane 16 handles s1 -- the two
        // expf->store chains run in parallel lanes.
        if (lane == 0)  emit_pl(s0, base + k,     l0, out, target);
        if (lane == 16) emit_pl(s1, base + k + 8, l1, out, target);
    }

    // Remainder (warps 0,1: k = 168,169)
    if (k < HS_PD) {
        const int idx = __ldg(paths + base + k);
        const int l   = __ldg(labels + base + k);
        const float4* __restrict__ row =
            reinterpret_cast<const float4*>(emb2 + (size_t)idx * HS_DIM);

        float4 a0 = __ldg(row + lane);
        float4 a1 = __ldg(row + lane + 32);
        float4 a2 = z;
        if (tail) a2 = __ldg(row + lane + 64);

        float s = dot4(a0, p0) + dot4(a1, p1) + dot4(a2, p2);

        #pragma unroll
        for (int off = 16; off > 0; off >>= 1)
            s += __shfl_xor_sync(0xffffffffu, s, off);

        if (lane == 0) emit_pl(s, base + k, l, out, target);
    }
}

extern "C" void kernel_launch(void* const* d_in, const int* in_sizes, int n_in,
                              void* d_out, int out_size)
{
    // metadata order: word_idx, paths, labels, emb1, emb2
    const int*   word_idx = (const int*)  d_in[0];
    const int*   paths    = (const int*)  d_in[1];
    const int*   labels   = (const int*)  d_in[2];
    const float* emb1     = (const float*)d_in[3];
    const float* emb2     = (const float*)d_in[4];

    float* out    = (float*)d_out;                        // first N*P*D: sigmoid
    float* target = (float*)d_out + (size_t)HS_N * HS_PD; // second N*P*D: target

    skip_gram_hs_kernel<<<HS_N, 256>>>(word_idx, paths, labels, emb1, emb2,
                                       out, target);
}

// round 14
// speedup vs baseline: 1.3676x; 1.1966x over previous
#include <cuda_runtime.h>

// Problem constants (fixed by the reference)
#define HS_N    4096
#define HS_P    10
#define HS_D    17
#define HS_PD   (HS_P * HS_D)   // 170 dot products per sample
#define HS_DIM  300             // embedding dim (75 float4)
#define HS_VEC4 (HS_DIM / 4)    // 75

__device__ __forceinline__ float dot4(float4 a, float4 b) {
    return a.x * b.x + a.y * b.y + a.z * b.z + a.w * b.w;
}

__global__ __launch_bounds__(256)
void skip_gram_hs_kernel(const int*   __restrict__ word_idx,   // [N]
                         const int*   __restrict__ paths,      // [N, P, D]
                         const int*   __restrict__ labels,     // [N, P, D]
                         const float* __restrict__ emb1,       // [VOCAB, DIM]
                         const float* __restrict__ emb2,       // [VOCAB-1, DIM]
                         float*       __restrict__ out,        // [N, P, D]
                         float*       __restrict__ target)     // [N, P, D]
{
    // Block-wide staging of indices+labels: removes two serialized L2
    // round-trips (~480 cyc) from every inner iteration's critical path,
    // at ZERO register cost (the 32-reg / 8-block boundary is sacred:
    // every register-funded variant regressed).
    __shared__ int s_idx[HS_PD];
    __shared__ int s_lab[HS_PD];

    const int n    = blockIdx.x;
    const int tid  = threadIdx.x;
    const int warp = tid >> 5;
    const int lane = tid & 31;
    const bool tail = (lane < HS_VEC4 - 64);   // lanes 0..10 own float4 #64..74

    const int base = n * HS_PD;

    if (tid < HS_PD) {
        s_idx[tid] = paths[base + tid];
        s_lab[tid] = labels[base + tid];
    }

    // proj = emb1[word_idx[n]] in registers per lane (overlaps the staging).
    const int w = __ldg(word_idx + n);
    const float4* __restrict__ prow =
        reinterpret_cast<const float4*>(emb1 + (size_t)w * HS_DIM);
    const float4 p0 = __ldg(prow + lane);
    const float4 p1 = __ldg(prow + lane + 32);
    const float4 p2 = tail ? __ldg(prow + lane + 64) : make_float4(0.f, 0.f, 0.f, 0.f);

    __syncthreads();

    const float4 z = make_float4(0.f, 0.f, 0.f, 0.f);

    // 8 warps; each processes k = warp, warp+8, ... (~21 dot products),
    // two at a time for load MLP. Identical math/tree to the passing R5
    // kernel -> bit-identical outputs.
    int k = warp;
    for (; k + 8 < HS_PD; k += 16) {
        const int idx0 = s_idx[k];          // LDS broadcast, ~29 cyc
        const int idx1 = s_idx[k + 8];
        const float4* __restrict__ r0 =
            reinterpret_cast<const float4*>(emb2 + (size_t)idx0 * HS_DIM);
        const float4* __restrict__ r1 =
            reinterpret_cast<const float4*>(emb2 + (size_t)idx1 * HS_DIM);

        // Issue all 6 wide loads before consuming.
        float4 a0 = __ldg(r0 + lane);
        float4 a1 = __ldg(r0 + lane + 32);
        float4 b0 = __ldg(r1 + lane);
        float4 b1 = __ldg(r1 + lane + 32);
        float4 a2 = z, b2 = z;
        if (tail) { a2 = __ldg(r0 + lane + 64); b2 = __ldg(r1 + lane + 64); }

        float s0 = dot4(a0, p0) + dot4(a1, p1) + dot4(a2, p2);
        float s1 = dot4(b0, p0) + dot4(b1, p1) + dot4(b2, p2);

        // Two independent butterfly chains, interleaved.
        #pragma unroll
        for (int off = 16; off > 0; off >>= 1) {
            s0 += __shfl_xor_sync(0xffffffffu, s0, off);
            s1 += __shfl_xor_sync(0xffffffffu, s1, off);
        }

        if (lane == 0) {
            const float o0 = 1.0f / (1.0f + expf(-s0));
            const float o1 = 1.0f / (1.0f + expf(-s1));
            // Threshold the f32 sigmoid VALUE (matches reference rounding at 0.5).
            const int m0 = (o0 >= 0.5f) ? 1 : 0;
            const int m1 = (o1 >= 0.5f) ? 1 : 0;
            const int l0 = s_lab[k];        // LDS, no L2 trip
            const int l1 = s_lab[k + 8];
            out[base + k]        = o0;
            out[base + k + 8]    = o1;
            target[base + k]     = (m0 == l0) ? 1.0f : 0.0f;
            target[base + k + 8] = (m1 == l1) ? 1.0f : 0.0f;
        }
    }

    // Remainder (warps 0..7 where k+8 >= 170; at most one k)
    if (k < HS_PD) {
        const int idx = s_idx[k];
        const float4* __restrict__ row =
            reinterpret_cast<const float4*>(emb2 + (size_t)idx * HS_DIM);

        float4 a0 = __ldg(row + lane);
        float4 a1 = __ldg(row + lane + 32);
        float4 a2 = z;
        if (tail) a2 = __ldg(row + lane + 64);

        float s = dot4(a0, p0) + dot4(a1, p1) + dot4(a2, p2);

        #pragma unroll
        for (int off = 16; off > 0; off >>= 1)
            s += __shfl_xor_sync(0xffffffffu, s, off);

        if (lane == 0) {
            const float o = 1.0f / (1.0f + expf(-s));
            const int m = (o >= 0.5f) ? 1 : 0;
            const int l = s_lab[k];
            out[base + k]    = o;
            target[base + k] = (m == l) ? 1.0f : 0.0f;
        }
    }
}

extern "C" void kernel_launch(void* const* d_in, const int* in_sizes, int n_in,
                              void* d_out, int out_size)
{
    // metadata order: word_idx, paths, labels, emb1, emb2
    const int*   word_idx = (const int*)  d_in[0];
    const int*   paths    = (const int*)  d_in[1];
    const int*   labels   = (const int*)  d_in[2];
    const float* emb1     = (const float*)d_in[3];
    const float* emb2     = (const float*)d_in[4];

    float* out    = (float*)d_out;                        // first N*P*D: sigmoid
    float* target = (float*)d_out + (size_t)HS_N * HS_PD; // second N*P*D: target

    skip_gram_hs_kernel<<<HS_N, 256>>>(word_idx, paths, labels, emb1, emb2,
                                       out, target);
}

// round 15
// speedup vs baseline: 1.4077x; 1.0293x over previous
#include <cuda_runtime.h>

// Problem constants (fixed by the reference)
#define HS_N    4096
#define HS_P    10
#define HS_D    17
#define HS_PD   (HS_P * HS_D)   // 170 dot products per sample
#define HS_DIM  300             // embedding dim (75 float4)
#define HS_VEC4 (HS_DIM / 4)    // 75

__device__ __forceinline__ float dot4(float4 a, float4 b) {
    return a.x * b.x + a.y * b.y + a.z * b.z + a.w * b.w;
}

// emb2 row load, marked evict_last under a FRACTIONAL policy: ~90% of table
// lines (address-hashed) become L2-resident-protected (~108MB of the 120MB
// table fits the 126MB L2); streaming traffic can only evict the other 10%.
// (fraction 1.0 was a measured no-op in R9: all-marked == no differentiation.)
__device__ __forceinline__ float4 ldg_pol(const float4* p, unsigned long long pol) {
    float4 v;
    asm("ld.global.nc.L2::cache_hint.v4.f32 {%0,%1,%2,%3}, [%4], %5;"
        : "=f"(v.x), "=f"(v.y), "=f"(v.z), "=f"(v.w)
        : "l"(p), "l"(pol));
    return v;
}

__global__ __launch_bounds__(256)
void skip_gram_hs_kernel(const int*   __restrict__ word_idx,   // [N]
                         const int*   __restrict__ paths,      // [N, P, D]
                         const int*   __restrict__ labels,     // [N, P, D]
                         const float* __restrict__ emb1,       // [VOCAB, DIM]
                         const float* __restrict__ emb2,       // [VOCAB-1, DIM]
                         float*       __restrict__ out,        // [N, P, D]
                         float*       __restrict__ target)     // [N, P, D]
{
    __shared__ int s_idx[HS_PD];
    __shared__ int s_lab[HS_PD];

    const int n    = blockIdx.x;
    const int tid  = threadIdx.x;
    const int warp = tid >> 5;
    const int lane = tid & 31;
    const bool tail = (lane < HS_VEC4 - 64);   // lanes 0..10 own float4 #64..74

    unsigned long long pol;
    asm("createpolicy.fractional.L2::evict_last.b64 %0, 0.9;" : "=l"(pol));

    const int base = n * HS_PD;

    // Stage indices+labels with STREAMING loads (evict_first: read once,
    // must not displace protected table lines).
    if (tid < HS_PD) {
        s_idx[tid] = __ldcs(paths + base + tid);
        s_lab[tid] = __ldcs(labels + base + tid);
    }

    // proj = emb1[word_idx[n]] in registers per lane (overlaps the staging).
    const int w = __ldg(word_idx + n);
    const float4* __restrict__ prow =
        reinterpret_cast<const float4*>(emb1 + (size_t)w * HS_DIM);
    const float4 p0 = __ldg(prow + lane);
    const float4 p1 = __ldg(prow + lane + 32);
    const float4 p2 = tail ? __ldg(prow + lane + 64) : make_float4(0.f, 0.f, 0.f, 0.f);

    __syncthreads();

    const float4 z = make_float4(0.f, 0.f, 0.f, 0.f);

    // 8 warps; each processes k = warp, warp+8, ... (~21 dot products),
    // two at a time for load MLP. Identical math/tree to R13 -> bit-identical.
    int k = warp;
    for (; k + 8 < HS_PD; k += 16) {
        const int idx0 = s_idx[k];          // LDS broadcast
        const int idx1 = s_idx[k + 8];
        const float4* __restrict__ r0 =
            reinterpret_cast<const float4*>(emb2 + (size_t)idx0 * HS_DIM);
        const float4* __restrict__ r1 =
            reinterpret_cast<const float4*>(emb2 + (size_t)idx1 * HS_DIM);

        // Issue all 6 wide loads before consuming.
        float4 a0 = ldg_pol(r0 + lane, pol);
        float4 a1 = ldg_pol(r0 + lane + 32, pol);
        float4 b0 = ldg_pol(r1 + lane, pol);
        float4 b1 = ldg_pol(r1 + lane + 32, pol);
        float4 a2 = z, b2 = z;
        if (tail) { a2 = ldg_pol(r0 + lane + 64, pol); b2 = ldg_pol(r1 + lane + 64, pol); }

        float s0 = dot4(a0, p0) + dot4(a1, p1) + dot4(a2, p2);
        float s1 = dot4(b0, p0) + dot4(b1, p1) + dot4(b2, p2);

        // Two independent butterfly chains, interleaved.
        #pragma unroll
        for (int off = 16; off > 0; off >>= 1) {
            s0 += __shfl_xor_sync(0xffffffffu, s0, off);
            s1 += __shfl_xor_sync(0xffffffffu, s1, off);
        }

        if (lane == 0) {
            const float o0 = 1.0f / (1.0f + expf(-s0));
            const float o1 = 1.0f / (1.0f + expf(-s1));
            // Threshold the f32 sigmoid VALUE (matches reference rounding at 0.5).
            const int m0 = (o0 >= 0.5f) ? 1 : 0;
            const int m1 = (o1 >= 0.5f) ? 1 : 0;
            const int l0 = s_lab[k];
            const int l1 = s_lab[k + 8];
            // Streaming stores: write-once outputs must not evict table lines.
            __stcs(out + base + k,        o0);
            __stcs(out + base + k + 8,    o1);
            __stcs(target + base + k,     (m0 == l0) ? 1.0f : 0.0f);
            __stcs(target + base + k + 8, (m1 == l1) ? 1.0f : 0.0f);
        }
    }

    // Remainder (at most one k per warp)
    if (k < HS_PD) {
        const int idx = s_idx[k];
        const float4* __restrict__ row =
            reinterpret_cast<const float4*>(emb2 + (size_t)idx * HS_DIM);

        float4 a0 = ldg_pol(row + lane, pol);
        float4 a1 = ldg_pol(row + lane + 32, pol);
        float4 a2 = z;
        if (tail) a2 = ldg_pol(row + lane + 64, pol);

        float s = dot4(a0, p0) + dot4(a1, p1) + dot4(a2, p2);

        #pragma unroll
        for (int off = 16; off > 0; off >>= 1)
            s += __shfl_xor_sync(0xffffffffu, s, off);

        if (lane == 0) {
            const float o = 1.0f / (1.0f + expf(-s));
            const int m = (o >= 0.5f) ? 1 : 0;
            const int l = s_lab[k];
            __stcs(out + base + k,    o);
            __stcs(target + base + k, (m == l) ? 1.0f : 0.0f);
        }
    }
}

extern "C" void kernel_launch(void* const* d_in, const int* in_sizes, int n_in,
                              void* d_out, int out_size)
{
    // metadata order: word_idx, paths, labels, emb1, emb2
    const int*   word_idx = (const int*)  d_in[0];
    const int*   paths    = (const int*)  d_in[1];
    const int*   labels   = (const int*)  d_in[2];
    const float* emb1     = (const float*)d_in[3];
    const float* emb2     = (const float*)d_in[4];

    float* out    = (float*)d_out;                        // first N*P*D: sigmoid
    float* target = (float*)d_out + (size_t)HS_N * HS_PD; // second N*P*D: target

    skip_gram_hs_kernel<<<HS_N, 256>>>(word_idx, paths, labels, emb1, emb2,
                                       out, target);
}

// round 16
// speedup vs baseline: 1.5126x; 1.0746x over previous
#include <cuda_runtime.h>

// Problem constants (fixed by the reference)
#define HS_N    4096
#define HS_P    10
#define HS_D    17
#define HS_PD   (HS_P * HS_D)   // 170 dot products per sample
#define HS_DIM  300             // embedding dim (75 float4)
#define HS_VEC4 (HS_DIM / 4)    // 75

__device__ __forceinline__ float dot4(float4 a, float4 b) {
    return a.x * b.x + a.y * b.y + a.z * b.z + a.w * b.w;
}

__device__ __forceinline__ float4 ldg_pol(const float4* p, unsigned long long pol) {
    float4 v;
    asm("ld.global.nc.L2::cache_hint.v4.f32 {%0,%1,%2,%3}, [%4], %5;"
        : "=f"(v.x), "=f"(v.y), "=f"(v.z), "=f"(v.w)
        : "l"(p), "l"(pol));
    return v;
}

__device__ __forceinline__ void prefetch_l2(const void* p) {
    asm volatile("prefetch.global.L2 [%0];" :: "l"(p));
}

__global__ __launch_bounds__(256)
void skip_gram_hs_kernel(const int*   __restrict__ word_idx,   // [N]
                         const int*   __restrict__ paths,      // [N, P, D]
                         const int*   __restrict__ labels,     // [N, P, D]
                         const float* __restrict__ emb1,       // [VOCAB, DIM]
                         const float* __restrict__ emb2,       // [VOCAB-1, DIM]
                         float*       __restrict__ out,        // [N, P, D]
                         float*       __restrict__ target)     // [N, P, D]
{
    __shared__ int s_idx[HS_PD];
    __shared__ int s_lab[HS_PD];

    const int n    = blockIdx.x;
    const int tid  = threadIdx.x;
    const int warp = tid >> 5;
    const int lane = tid & 31;
    const bool tail = (lane < HS_VEC4 - 64);   // lanes 0..10 own float4 #64..74

    unsigned long long pol;
    asm("createpolicy.fractional.L2::evict_last.b64 %0, 0.9;" : "=l"(pol));

    const int base = n * HS_PD;

    // Stage indices+labels (streaming: read-once data).
    if (tid < HS_PD) {
        s_idx[tid] = __ldcs(paths + base + tid);
        s_lab[tid] = __ldcs(labels + base + tid);
    }

    // proj = emb1[word_idx[n]] in registers per lane (overlaps the staging).
    const int w = __ldg(word_idx + n);
    const float4* __restrict__ prow =
        reinterpret_cast<const float4*>(emb1 + (size_t)w * HS_DIM);
    const float4 p0 = __ldg(prow + lane);
    const float4 p1 = __ldg(prow + lane + 32);
    const float4 p2 = tail ? __ldg(prow + lane + 64) : make_float4(0.f, 0.f, 0.f, 0.f);

    __syncthreads();

    const float4 z = make_float4(0.f, 0.f, 0.f, 0.f);

    // Distance-1 L2 prefetch: while iteration k's ~650-cyc chain drains,
    // pair k+16's lines complete their DRAM hop into L2. Addresses are
    // consumed immediately (no live-range growth -> regs stay at 32).
    int k = warp;
    for (; k + 8 < HS_PD; k += 16) {
        // Prefetch next pair's rows (lanes 0..21: 11 lines x 2 rows; clamp
        // near the tail -> duplicate prefetch of current pair, harmless).
        {
            const int kn  = (k + 16 < HS_PD) ? k + 16 : k;
            const int kn8 = (k + 24 < HS_PD) ? k + 24 : kn;
            if (lane < 22) {
                const int idn = (lane & 1) ? s_idx[kn8] : s_idx[kn];
                const char* pn = reinterpret_cast<const char*>(emb2 + (size_t)idn * HS_DIM)
                               + (lane >> 1) * 128;
                prefetch_l2(pn);
            }
        }

        const int idx0 = s_idx[k];          // LDS broadcast
        const int idx1 = s_idx[k + 8];
        const float4* __restrict__ r0 =
            reinterpret_cast<const float4*>(emb2 + (size_t)idx0 * HS_DIM);
        const float4* __restrict__ r1 =
            reinterpret_cast<const float4*>(emb2 + (size_t)idx1 * HS_DIM);

        // Issue all 6 wide loads before consuming.
        float4 a0 = ldg_pol(r0 + lane, pol);
        float4 a1 = ldg_pol(r0 + lane + 32, pol);
        float4 b0 = ldg_pol(r1 + lane, pol);
        float4 b1 = ldg_pol(r1 + lane + 32, pol);
        float4 a2 = z, b2 = z;
        if (tail) { a2 = ldg_pol(r0 + lane + 64, pol); b2 = ldg_pol(r1 + lane + 64, pol); }

        float s0 = dot4(a0, p0) + dot4(a1, p1) + dot4(a2, p2);
        float s1 = dot4(b0, p0) + dot4(b1, p1) + dot4(b2, p2);

        // Two independent butterfly chains, interleaved (tree identical to
        // R5/R13/R14 -> bit-identical outputs).
        #pragma unroll
        for (int off = 16; off > 0; off >>= 1) {
            s0 += __shfl_xor_sync(0xffffffffu, s0, off);
            s1 += __shfl_xor_sync(0xffffffffu, s1, off);
        }

        if (lane == 0) {
            const float o0 = 1.0f / (1.0f + expf(-s0));
            const float o1 = 1.0f / (1.0f + expf(-s1));
            // Threshold the f32 sigmoid VALUE (matches reference rounding at 0.5).
            const int m0 = (o0 >= 0.5f) ? 1 : 0;
            const int m1 = (o1 >= 0.5f) ? 1 : 0;
            const int l0 = s_lab[k];
            const int l1 = s_lab[k + 8];
            __stcs(out + base + k,        o0);
            __stcs(out + base + k + 8,    o1);
            __stcs(target + base + k,     (m0 == l0) ? 1.0f : 0.0f);
            __stcs(target + base + k + 8, (m1 == l1) ? 1.0f : 0.0f);
        }
    }

    // Remainder (at most one k per warp)
    if (k < HS_PD) {
        const int idx = s_idx[k];
        const float4* __restrict__ row =
            reinterpret_cast<const float4*>(emb2 + (size_t)idx * HS_DIM);

        float4 a0 = ldg_pol(row + lane, pol);
        float4 a1 = ldg_pol(row + lane + 32, pol);
        float4 a2 = z;
        if (tail) a2 = ldg_pol(row + lane + 64, pol);

        float s = dot4(a0, p0) + dot4(a1, p1) + dot4(a2, p2);

        #pragma unroll
        for (int off = 16; off > 0; off >>= 1)
            s += __shfl_xor_sync(0xffffffffu, s, off);

        if (lane == 0) {
            const float o = 1.0f / (1.0f + expf(-s));
            const int m = (o >= 0.5f) ? 1 : 0;
            const int l = s_lab[k];
            __stcs(out + base + k,    o);
            __stcs(target + base + k, (m == l) ? 1.0f : 0.0f);
        }
    }
}

extern "C" void kernel_launch(void* const* d_in, const int* in_sizes, int n_in,
                              void* d_out, int out_size)
{
    // metadata order: word_idx, paths, labels, emb1, emb2
    const int*   word_idx = (const int*)  d_in[0];
    const int*   paths    = (const int*)  d_in[1];
    const int*   labels   = (const int*)  d_in[2];
    const float* emb1     = (const float*)d_in[3];
    const float* emb2     = (const float*)d_in[4];

    float* out    = (float*)d_out;                        // first N*P*D: sigmoid
    float* target = (float*)d_out + (size_t)HS_N * HS_PD; // second N*P*D: target

    skip_gram_hs_kernel<<<HS_N, 256>>>(word_idx, paths, labels, emb1, emb2,
                                       out, target);
}